// round 15
// baseline (speedup 1.0000x reference)
#include <cuda_runtime.h>
#include <cuda_fp16.h>
#include <math.h>

#define NN 50000
#define NP 50176          // padded rows (multiple of 128)
#define NE 800000
#define FI 256
#define NH 8
#define HD 64
#define C1 512
#define NC 40
#define LRELU_SLOPE 0.2f

// ---------------- static scratch ----------------
// H1 flat fp16: [node][512]
__device__ __align__(16) __half g_H1[(size_t)NN * C1];
__device__ float g_ASRC1[NN * NH];
__device__ float g_ATGT1[NN * NH];
__device__ float g_H2[NN * NC];
__device__ float g_ASRC2[NN];
__device__ float g_ATGT2[NN];
__device__ int   g_CNT[NN];
__device__ int   g_OFFS[NN + 1];
__device__ int   g_CURSOR[NN];
__device__ int   g_TSORT[NE];
__device__ int   g_AUX[128];

// fp16 operands
__device__ __align__(16) __half g_XF[(size_t)NP * FI];      // x fp16
__device__ __align__(16) __half g_W1F[C1 * FI];             // W1ᵗ [col512][k256]
__device__ __align__(16) __half g_W2F[NC * C1];             // W2ᵗ [col40][k512]
__device__ __align__(16) __half g_EF[(size_t)NP * C1];      // ELU(OUT1+b1) fp16

// ---------------- helpers ----------------
__device__ __forceinline__ float lrelu(float v) { return v > 0.f ? v : LRELU_SLOPE * v; }
__device__ __forceinline__ float eluf(float v)  { return v > 0.f ? v : expm1f(v); }

__device__ __forceinline__ float wsum(float v) {
#pragma unroll
    for (int o = 16; o; o >>= 1) v += __shfl_xor_sync(0xffffffffu, v, o);
    return v;
}
__device__ __forceinline__ float wmax(float v) {
#pragma unroll
    for (int o = 16; o; o >>= 1) v = fmaxf(v, __shfl_xor_sync(0xffffffffu, v, o));
    return v;
}

__device__ __forceinline__ unsigned smem_u32(const void* p) {
    return (unsigned)__cvta_generic_to_shared(p);
}

__device__ __forceinline__ void ldm4(unsigned& r0, unsigned& r1, unsigned& r2, unsigned& r3,
                                     unsigned addr) {
    asm volatile("ldmatrix.sync.aligned.m8n8.x4.shared.b16 {%0,%1,%2,%3}, [%4];"
                 : "=r"(r0), "=r"(r1), "=r"(r2), "=r"(r3) : "r"(addr));
}

__device__ __forceinline__ void mmaf16(float* c, const unsigned* a, const unsigned* b) {
    asm volatile("mma.sync.aligned.m16n8k16.row.col.f32.f16.f16.f32 "
                 "{%0,%1,%2,%3}, {%4,%5,%6,%7}, {%8,%9}, {%0,%1,%2,%3};"
                 : "+f"(c[0]), "+f"(c[1]), "+f"(c[2]), "+f"(c[3])
                 : "r"(a[0]), "r"(a[1]), "r"(a[2]), "r"(a[3]), "r"(b[0]), "r"(b[1]));
}

// ---------------- init ----------------
__global__ void zero_all_kernel() {
    int i = blockIdx.x * blockDim.x + threadIdx.x;
    if (i < NN) g_CNT[i] = 0;
    if (i < (NP - NN) * C1) g_EF[(size_t)NN * C1 + i] = __float2half(0.f);
}

// ---------------- combined prep ----------------
#define PX_ITEMS (NP * FI / 4)
#define PW1_ITEMS (C1 * FI)
#define PW2_ITEMS (NC * C1)

__global__ void prep_all_kernel(const float* __restrict__ x,
                                const float* __restrict__ W1,
                                const float* __restrict__ W2) {
    int i = blockIdx.x * blockDim.x + threadIdx.x;
    if (i < PX_ITEMS) {
        int row = i >> 6;
        float4 v = (row < NN) ? *(const float4*)(x + (size_t)i * 4)
                              : make_float4(0.f, 0.f, 0.f, 0.f);
        __half2 h0 = __floats2half2_rn(v.x, v.y);
        __half2 h1 = __floats2half2_rn(v.z, v.w);
        *(__half2*)&g_XF[(size_t)i * 4]     = h0;
        *(__half2*)&g_XF[(size_t)i * 4 + 2] = h1;
    } else if (i < PX_ITEMS + PW1_ITEMS) {
        int idx = i - PX_ITEMS;
        int c = idx >> 8;
        int k = idx & 255;
        g_W1F[idx] = __float2half(W1[(size_t)(c >> 6) * (FI * HD) + (size_t)k * HD + (c & 63)]);
    } else if (i < PX_ITEMS + PW1_ITEMS + PW2_ITEMS) {
        int idx = i - PX_ITEMS - PW1_ITEMS;
        int c = idx >> 9;
        int k = idx & 511;
        g_W2F[idx] = __float2half(W2[(size_t)k * NC + c]);
    }
}

// ---------------- GEMM1: 1-pass fp16 mma.sync, 2 CTA/SM, fused a1 dots ----------------
__global__ __launch_bounds__(256, 2) void gemm1_mma_kernel(const float* __restrict__ a1p) {
    __shared__ unsigned AH[2][128][12];
    __shared__ unsigned BH[2][128][12];

    const int tid  = threadIdx.x;
    const int lane = tid & 31;
    const int wid  = tid >> 5;
    const int wm   = wid >> 1;
    const int wn   = wid & 1;
    const int bm   = blockIdx.x * 128;
    const int bn   = blockIdx.y * 128;

    float acc[2][8][4];
#pragma unroll
    for (int i = 0; i < 2; i++)
#pragma unroll
        for (int j = 0; j < 8; j++)
#pragma unroll
            for (int k = 0; k < 4; k++) acc[i][j][k] = 0.f;

    const unsigned aBase = smem_u32(AH);
    const unsigned bBase = smem_u32(BH);
    const unsigned BUF = 128 * 48;     // bytes per buffer

    unsigned aadr[2];
#pragma unroll
    for (int mt = 0; mt < 2; mt++) {
        int r = wm * 32 + mt * 16 + (lane & 15);
        int cb = (lane >> 4) * 16;
        aadr[mt] = aBase + r * 48 + cb;
    }
    unsigned badr[4];
#pragma unroll
    for (int np = 0; np < 4; np++) {
        int r = wn * 64 + np * 16 + ((lane >> 4) << 3) + (lane & 7);
        int cb = ((lane >> 3) & 1) * 16;
        badr[np] = bBase + r * 48 + cb;
    }

    const int arow = tid >> 1;
    const int ach  = tid & 1;
    const unsigned short* xf = (const unsigned short*)g_XF;
    const unsigned short* wf = (const unsigned short*)g_W1F;
    size_t aIdx = (size_t)(bm + arow) * FI + ach * 8;
    size_t bIdx = (size_t)(bn + arow) * FI + ach * 8;

    // preload tile 0 into buf 0
    *(uint4*)&AH[0][arow][ach * 4] = *(const uint4*)(xf + aIdx);
    *(uint4*)&BH[0][arow][ach * 4] = *(const uint4*)(wf + bIdx);
    __syncthreads();

    for (int it = 0; it < 16; ++it) {
        const int b = it & 1;
        const unsigned boff = b * BUF;

        unsigned ah[2][4];
#pragma unroll
        for (int mt = 0; mt < 2; mt++)
            ldm4(ah[mt][0], ah[mt][1], ah[mt][2], ah[mt][3], aadr[mt] + boff);

        uint4 va, vb;
        if (it < 15) {
            const int k1 = (it + 1) * 16;
            va = *(const uint4*)(xf + aIdx + k1);
            vb = *(const uint4*)(wf + bIdx + k1);
        }

#pragma unroll
        for (int np = 0; np < 4; np++) {
            unsigned bh[4];
            ldm4(bh[0], bh[1], bh[2], bh[3], badr[np] + boff);
#pragma unroll
            for (int mt = 0; mt < 2; mt++) {
                mmaf16(acc[mt][np * 2],     ah[mt], bh);
                mmaf16(acc[mt][np * 2 + 1], ah[mt], bh + 2);
            }
        }

        if (it < 15) {
            int nb = b ^ 1;
            *(uint4*)&AH[nb][arow][ach * 4] = va;
            *(uint4*)&BH[nb][arow][ach * 4] = vb;
        }
        __syncthreads();
    }

    // write H1 fp16 (flat [node][512])
    const int cbase = bn + wn * 64 + (lane & 3) * 2;
#pragma unroll
    for (int mt = 0; mt < 2; mt++) {
        int r = bm + wm * 32 + mt * 16 + (lane >> 2);
#pragma unroll
        for (int nt = 0; nt < 8; nt++) {
            if (r < NN) {
                __half2 hv = __floats2half2_rn(acc[mt][nt][0], acc[mt][nt][1]);
                *(__half2*)&g_H1[(size_t)r * C1 + cbase + nt * 8] = hv;
            }
            if (r + 8 < NN) {
                __half2 hv = __floats2half2_rn(acc[mt][nt][2], acc[mt][nt][3]);
                *(__half2*)&g_H1[(size_t)(r + 8) * C1 + cbase + nt * 8] = hv;
            }
        }
    }

    // fused a1 dots
    const int hh = blockIdx.y * 2 + wn;
    const float* av = a1p + hh * (2 * HD);
    const float* tv = av + HD;
    float sdot[4], tdot[4];
#pragma unroll
    for (int i = 0; i < 4; i++) { sdot[i] = 0.f; tdot[i] = 0.f; }
#pragma unroll
    for (int mt = 0; mt < 2; mt++) {
#pragma unroll
        for (int nt = 0; nt < 8; nt++) {
            int cip = nt * 8 + (lane & 3) * 2;
            float a0 = __ldg(av + cip);
            float a1e = __ldg(av + cip + 1);
            float t0 = __ldg(tv + cip);
            float t1e = __ldg(tv + cip + 1);
            sdot[mt * 2 + 0] += acc[mt][nt][0] * a0 + acc[mt][nt][1] * a1e;
            tdot[mt * 2 + 0] += acc[mt][nt][0] * t0 + acc[mt][nt][1] * t1e;
            sdot[mt * 2 + 1] += acc[mt][nt][2] * a0 + acc[mt][nt][3] * a1e;
            tdot[mt * 2 + 1] += acc[mt][nt][2] * t0 + acc[mt][nt][3] * t1e;
        }
    }
#pragma unroll
    for (int i = 0; i < 4; i++) {
        sdot[i] += __shfl_xor_sync(0xffffffffu, sdot[i], 1);
        sdot[i] += __shfl_xor_sync(0xffffffffu, sdot[i], 2);
        tdot[i] += __shfl_xor_sync(0xffffffffu, tdot[i], 1);
        tdot[i] += __shfl_xor_sync(0xffffffffu, tdot[i], 2);
    }
    if ((lane & 3) == 0) {
#pragma unroll
        for (int mt = 0; mt < 2; mt++) {
#pragma unroll
            for (int hb = 0; hb < 2; hb++) {
                int r = bm + wm * 32 + mt * 16 + (lane >> 2) + hb * 8;
                if (r < NN) {
                    g_ASRC1[r * NH + hh] = sdot[mt * 2 + hb];
                    g_ATGT1[r * NH + hh] = tdot[mt * 2 + hb];
                }
            }
        }
    }
}

// ---------------- histogram ----------------
__global__ void hist_kernel(const int* __restrict__ src) {
    int e = blockIdx.x * blockDim.x + threadIdx.x;
    if (e >= NE) return;
    atomicAdd(&g_CNT[src[e]], 1);
}

// ---------------- counting-sort scan ----------------
#define SBLK 512
#define NBLK 98

__global__ void scan_block_kernel() {
    __shared__ int sh[SBLK];
    int t = threadIdx.x;
    int i = blockIdx.x * SBLK + t;
    int v = (i < NN) ? g_CNT[i] : 0;
    sh[t] = v;
    __syncthreads();
#pragma unroll
    for (int off = 1; off < SBLK; off <<= 1) {
        int add = (t >= off) ? sh[t - off] : 0;
        __syncthreads();
        sh[t] += add;
        __syncthreads();
    }
    if (i < NN) g_OFFS[i] = sh[t] - v;
    if (t == SBLK - 1) g_AUX[blockIdx.x] = sh[SBLK - 1];
}

// scan_add with aux prefix computed per-block in smem (scan_aux folded in)
__global__ void scan_add_kernel() {
    __shared__ int sh[128];
    int t = threadIdx.x;
    if (t < 128) sh[t] = (t < NBLK) ? g_AUX[t] : 0;
    __syncthreads();
#pragma unroll
    for (int off = 1; off < 128; off <<= 1) {
        int add = (t < 128 && t >= off) ? sh[t - off] : 0;
        __syncthreads();
        if (t < 128) sh[t] += add;
        __syncthreads();
    }
    int base = (blockIdx.x > 0) ? sh[blockIdx.x - 1] : 0;   // exclusive prefix
    int i = blockIdx.x * SBLK + t;
    if (i < NN) {
        int v = g_OFFS[i] + base;
        g_OFFS[i] = v;
        g_CURSOR[i] = v;
    }
    if (i == 0) g_OFFS[NN] = NE;
}

__global__ void sort_kernel(const int* __restrict__ src, const int* __restrict__ tgt) {
    int e = blockIdx.x * blockDim.x + threadIdx.x;
    if (e >= NE) return;
    int s = src[e];
    int pos = atomicAdd(&g_CURSOR[s], 1);
    g_TSORT[pos] = tgt[e];
}

// ---------------- gather1 one-pass (all 8 heads), unroll 2 ----------------
__global__ void gather1_kernel(const float* __restrict__ b1) {
    int w = (blockIdx.x * blockDim.x + threadIdx.x) >> 5;
    int lane = threadIdx.x & 31;
    if (w >= NN) return;
    int beg = g_OFFS[w];
    int end = g_OFFS[w + 1];
    int hsel = lane >> 4;                 // 0/1: which head within 128-col group
    float asrc = g_ASRC1[w * NH + (lane & 7)];
    float den[4] = {0.f, 0.f, 0.f, 0.f};
    float4 acc[4];
#pragma unroll
    for (int g = 0; g < 4; g++) acc[g] = make_float4(0.f, 0.f, 0.f, 0.f);

    int i = beg;
    for (; i + 2 <= end; i += 2) {
        int t0 = g_TSORT[i];
        int t1 = g_TSORT[i + 1];
        float e0 = expf(lrelu(asrc + g_ATGT1[t0 * NH + (lane & 7)]));
        float e1 = expf(lrelu(asrc + g_ATGT1[t1 * NH + (lane & 7)]));
        const __half* r0 = g_H1 + (size_t)t0 * C1;
        const __half* r1 = g_H1 + (size_t)t1 * C1;
#pragma unroll
        for (int g = 0; g < 4; g++) {
            float ev0 = __shfl_sync(0xffffffffu, e0, g * 2 + hsel, 8);
            float ev1 = __shfl_sync(0xffffffffu, e1, g * 2 + hsel, 8);
            den[g] += ev0 + ev1;
            float2 f0a = __half22float2(*(const __half2*)(r0 + g * 128 + lane * 4));
            float2 f0b = __half22float2(*(const __half2*)(r0 + g * 128 + lane * 4 + 2));
            float2 f1a = __half22float2(*(const __half2*)(r1 + g * 128 + lane * 4));
            float2 f1b = __half22float2(*(const __half2*)(r1 + g * 128 + lane * 4 + 2));
            acc[g].x += ev0 * f0a.x + ev1 * f1a.x;
            acc[g].y += ev0 * f0a.y + ev1 * f1a.y;
            acc[g].z += ev0 * f0b.x + ev1 * f1b.x;
            acc[g].w += ev0 * f0b.y + ev1 * f1b.y;
        }
    }
    if (i < end) {
        int t0 = g_TSORT[i];
        float e0 = expf(lrelu(asrc + g_ATGT1[t0 * NH + (lane & 7)]));
        const __half* r0 = g_H1 + (size_t)t0 * C1;
#pragma unroll
        for (int g = 0; g < 4; g++) {
            float ev0 = __shfl_sync(0xffffffffu, e0, g * 2 + hsel, 8);
            den[g] += ev0;
            float2 f0a = __half22float2(*(const __half2*)(r0 + g * 128 + lane * 4));
            float2 f0b = __half22float2(*(const __half2*)(r0 + g * 128 + lane * 4 + 2));
            acc[g].x += ev0 * f0a.x;
            acc[g].y += ev0 * f0a.y;
            acc[g].z += ev0 * f0b.x;
            acc[g].w += ev0 * f0b.y;
        }
    }
#pragma unroll
    for (int g = 0; g < 4; g++) {
        float r = 1.f / (den[g] + 1e-10f);
        int col = g * 128 + lane * 4;
        float4 bb = *(const float4*)&b1[col];
        float v0 = eluf(acc[g].x * r + bb.x);
        float v1 = eluf(acc[g].y * r + bb.y);
        float v2 = eluf(acc[g].z * r + bb.z);
        float v3 = eluf(acc[g].w * r + bb.w);
        size_t base = (size_t)w * C1 + col;
        *(__half2*)&g_EF[base]     = __floats2half2_rn(v0, v1);
        *(__half2*)&g_EF[base + 2] = __floats2half2_rn(v2, v3);
    }
}

// ---------------- GEMM2: 1-pass fp16, resident-B, double-buffered A, fused alpha2 -----
#define G2_BSTR 260                       // words per B row (1040 B)
#define G2_BWORDS (48 * G2_BSTR)
#define G2_AWORDS (2 * 128 * 12)
#define G2_SMEM_BYTES ((G2_BWORDS + G2_AWORDS) * 4)

__global__ __launch_bounds__(256) void gemm2_mma_kernel(const float* __restrict__ a2) {
    extern __shared__ unsigned g2s[];
    unsigned* sB = g2s;
    unsigned* sA = g2s + G2_BWORDS;     // [2][128][12]

    const int tid  = threadIdx.x;
    const int lane = tid & 31;
    const int wid  = tid >> 5;
    const int bm   = blockIdx.x * 128;

    for (int idx = tid; idx < 48 * 256; idx += 256) {
        int row = idx >> 8;
        int wq  = idx & 255;
        unsigned v = (row < NC) ? ((const unsigned*)g_W2F)[row * 256 + wq] : 0u;
        sB[row * G2_BSTR + wq] = v;
    }

    float acc[5][4];
#pragma unroll
    for (int j = 0; j < 5; j++)
#pragma unroll
        for (int k = 0; k < 4; k++) acc[j][k] = 0.f;

    const unsigned aBase = smem_u32(sA);
    const unsigned bBase = smem_u32(sB);
    const unsigned ABUF = 128 * 48;

    unsigned aadr;
    {
        int r = wid * 16 + (lane & 15);
        int cb = (lane >> 4) * 16;
        aadr = aBase + r * 48 + cb;
    }
    unsigned badr[3];
#pragma unroll
    for (int np = 0; np < 3; np++) {
        int r = np * 16 + ((lane >> 4) << 3) + (lane & 7);
        int cb = ((lane >> 3) & 1) * 16;
        badr[np] = bBase + r * (G2_BSTR * 4) + cb;
    }

    const int arow = tid >> 1;
    const int ach  = tid & 1;
    const unsigned short* ef = (const unsigned short*)g_EF;
    size_t aIdx = (size_t)(bm + arow) * C1 + ach * 8;

    *(uint4*)(sA + (size_t)arow * 12 + ach * 4) = *(const uint4*)(ef + aIdx);
    __syncthreads();

    for (int it = 0; it < 32; ++it) {
        const int b = it & 1;
        const unsigned aoff = b * ABUF;
        const unsigned koff = it * 32;

        unsigned ah[4];
        ldm4(ah[0], ah[1], ah[2], ah[3], aadr + aoff);

        uint4 va;
        if (it < 31) va = *(const uint4*)(ef + aIdx + (it + 1) * 16);

#pragma unroll
        for (int np = 0; np < 3; np++) {
            unsigned bh[4];
            ldm4(bh[0], bh[1], bh[2], bh[3], badr[np] + koff);
            mmaf16(acc[np * 2], ah, bh);
            if (np < 2) mmaf16(acc[np * 2 + 1], ah, bh + 2);
        }

        if (it < 31) {
            int nb = b ^ 1;
            *(uint4*)(sA + (size_t)nb * (128 * 12) + (size_t)arow * 12 + ach * 4) = va;
        }
        __syncthreads();
    }

    int r0 = bm + wid * 16 + (lane >> 2);
    int r1 = r0 + 8;
    float s0 = 0.f, s1 = 0.f, t0 = 0.f, t1 = 0.f;
#pragma unroll
    for (int nt = 0; nt < 5; nt++) {
        int c = nt * 8 + (lane & 3) * 2;
        float a0 = __ldg(a2 + c);
        float a1e = __ldg(a2 + c + 1);
        float b0 = __ldg(a2 + NC + c);
        float b1e = __ldg(a2 + NC + c + 1);
        if (r0 < NN) {
            float2 v;
            v.x = acc[nt][0];
            v.y = acc[nt][1];
            *(float2*)&g_H2[(size_t)r0 * NC + c] = v;
        }
        if (r1 < NN) {
            float2 v;
            v.x = acc[nt][2];
            v.y = acc[nt][3];
            *(float2*)&g_H2[(size_t)r1 * NC + c] = v;
        }
        s0 += acc[nt][0] * a0 + acc[nt][1] * a1e;
        t0 += acc[nt][0] * b0 + acc[nt][1] * b1e;
        s1 += acc[nt][2] * a0 + acc[nt][3] * a1e;
        t1 += acc[nt][2] * b0 + acc[nt][3] * b1e;
    }
    s0 += __shfl_xor_sync(0xffffffffu, s0, 1);
    s0 += __shfl_xor_sync(0xffffffffu, s0, 2);
    s1 += __shfl_xor_sync(0xffffffffu, s1, 1);
    s1 += __shfl_xor_sync(0xffffffffu, s1, 2);
    t0 += __shfl_xor_sync(0xffffffffu, t0, 1);
    t0 += __shfl_xor_sync(0xffffffffu, t0, 2);
    t1 += __shfl_xor_sync(0xffffffffu, t1, 1);
    t1 += __shfl_xor_sync(0xffffffffu, t1, 2);
    if ((lane & 3) == 0) {
        if (r0 < NN) {
            g_ASRC2[r0] = s0;
            g_ATGT2[r0] = t0;
        }
        if (r1 < NN) {
            g_ASRC2[r1] = s1;
            g_ATGT2[r1] = t1;
        }
    }
}

// ---------------- gather2 + log_softmax fused, unroll 2 ----------------
__global__ void gather2_logsm_kernel(const float* __restrict__ b2, float* __restrict__ out) {
    int w = (blockIdx.x * blockDim.x + threadIdx.x) >> 5;
    int lane = threadIdx.x & 31;
    if (w >= NN) return;
    int beg = g_OFFS[w];
    int end = g_OFFS[w + 1];
    float asrc = g_ASRC2[w];
    bool has2 = lane < 8;
    float acc1 = 0.f;
    float acc2 = 0.f;
    float den = 0.f;
    int i = beg;
    for (; i + 2 <= end; i += 2) {
        int t0 = g_TSORT[i];
        int t1 = g_TSORT[i + 1];
        float ev0 = expf(lrelu(asrc + g_ATGT2[t0]));
        float ev1 = expf(lrelu(asrc + g_ATGT2[t1]));
        den += ev0 + ev1;
        acc1 += ev0 * g_H2[t0 * NC + lane] + ev1 * g_H2[t1 * NC + lane];
        if (has2) acc2 += ev0 * g_H2[t0 * NC + 32 + lane] + ev1 * g_H2[t1 * NC + 32 + lane];
    }
    if (i < end) {
        int t = g_TSORT[i];
        float ev = expf(lrelu(asrc + g_ATGT2[t]));
        den += ev;
        acc1 += ev * g_H2[t * NC + lane];
        if (has2) acc2 += ev * g_H2[t * NC + 32 + lane];
    }
    float r = 1.f / (den + 1e-10f);
    float v1 = acc1 * r + b2[lane];
    float v2 = has2 ? (acc2 * r + b2[32 + lane]) : -3.0e38f;
    float m = wmax(fmaxf(v1, v2));
    float ssum = expf(v1 - m) + (has2 ? expf(v2 - m) : 0.f);
    ssum = wsum(ssum);
    float l = logf(ssum);
    out[w * NC + lane] = v1 - m - l;
    if (has2) out[w * NC + 32 + lane] = v2 - m - l;
}

// ---------------- launch ----------------
extern "C" void kernel_launch(void* const* d_in, const int* in_sizes, int n_in,
                              void* d_out, int out_size) {
    const float* x  = (const float*)d_in[0];
    const int*   el = (const int*)d_in[1];
    const float* W1 = (const float*)d_in[2];
    const float* a1 = (const float*)d_in[3];
    const float* b1 = (const float*)d_in[4];
    const float* W2 = (const float*)d_in[5];
    const float* a2 = (const float*)d_in[6];
    const float* b2 = (const float*)d_in[7];
    float* out = (float*)d_out;
    const int* src = el;
    const int* tgt = el + NE;

    cudaFuncSetAttribute(gemm2_mma_kernel,
                         cudaFuncAttributeMaxDynamicSharedMemorySize, G2_SMEM_BYTES);

    // order chosen so launch index 3 (the one ncu captures) is gemm1
    int prep_items = PX_ITEMS + PW1_ITEMS + PW2_ITEMS;
    prep_all_kernel<<<(prep_items + 255) / 256, 256>>>(x, W1, W2);       // 0
    zero_all_kernel<<<((NP - NN) * C1 + 255) / 256, 256>>>();            // 1
    hist_kernel<<<(NE + 255) / 256, 256>>>(src);                          // 2

    dim3 g1(NP / 128, C1 / 128);
    gemm1_mma_kernel<<<g1, 256>>>(a1);                                    // 3

    scan_block_kernel<<<NBLK, SBLK>>>();                                  // 4
    scan_add_kernel<<<NBLK, SBLK>>>();                                    // 5
    sort_kernel<<<(NE + 255) / 256, 256>>>(src, tgt);                     // 6

    int warp_grid = (NN * 32 + 255) / 256;
    gather1_kernel<<<warp_grid, 256>>>(b1);                               // 7

    gemm2_mma_kernel<<<NP / 128, 256, G2_SMEM_BYTES>>>(a2);               // 8
    gather2_logsm_kernel<<<warp_grid, 256>>>(b2, out);                    // 9
}

// round 16
// speedup vs baseline: 1.0241x; 1.0241x over previous
#include <cuda_runtime.h>
#include <cuda_fp16.h>
#include <math.h>

#define NN 50000
#define NP 50176          // padded rows (multiple of 128)
#define NE 800000
#define FI 256
#define NH 8
#define HD 64
#define C1 512
#define NC 40
#define LRELU_SLOPE 0.2f

// ---------------- static scratch ----------------
// H1 stored group-major fp16: [group(2)][node][256 cols]
__device__ __align__(16) __half g_H1[(size_t)2 * NN * 256];
__device__ float g_ASRC1[NN * NH];
__device__ float g_ATGT1[NN * NH];
__device__ float g_H2[NN * NC];
__device__ float g_ASRC2[NN];
__device__ float g_ATGT2[NN];
__device__ int   g_CNT[NN];
__device__ int   g_OFFS[NN + 1];
__device__ int   g_CURSOR[NN];
__device__ int   g_TSORT[NE];
__device__ int   g_AUX[128];

// fp16 operands
__device__ __align__(16) __half g_XF[(size_t)NP * FI];      // x fp16
__device__ __align__(16) __half g_W1F[C1 * FI];             // W1ᵗ [col512][k256]
__device__ __align__(16) __half g_W2F[NC * C1];             // W2ᵗ [col40][k512]
__device__ __align__(16) __half g_EF[(size_t)NP * C1];      // ELU(OUT1+b1) fp16

// ---------------- helpers ----------------
__device__ __forceinline__ float lrelu(float v) { return v > 0.f ? v : LRELU_SLOPE * v; }
__device__ __forceinline__ float eluf(float v)  { return v > 0.f ? v : expm1f(v); }

__device__ __forceinline__ float wsum(float v) {
#pragma unroll
    for (int o = 16; o; o >>= 1) v += __shfl_xor_sync(0xffffffffu, v, o);
    return v;
}
__device__ __forceinline__ float wmax(float v) {
#pragma unroll
    for (int o = 16; o; o >>= 1) v = fmaxf(v, __shfl_xor_sync(0xffffffffu, v, o));
    return v;
}

__device__ __forceinline__ unsigned smem_u32(const void* p) {
    return (unsigned)__cvta_generic_to_shared(p);
}

__device__ __forceinline__ void ldm4(unsigned& r0, unsigned& r1, unsigned& r2, unsigned& r3,
                                     unsigned addr) {
    asm volatile("ldmatrix.sync.aligned.m8n8.x4.shared.b16 {%0,%1,%2,%3}, [%4];"
                 : "=r"(r0), "=r"(r1), "=r"(r2), "=r"(r3) : "r"(addr));
}

__device__ __forceinline__ void mmaf16(float* c, const unsigned* a, const unsigned* b) {
    asm volatile("mma.sync.aligned.m16n8k16.row.col.f32.f16.f16.f32 "
                 "{%0,%1,%2,%3}, {%4,%5,%6,%7}, {%8,%9}, {%0,%1,%2,%3};"
                 : "+f"(c[0]), "+f"(c[1]), "+f"(c[2]), "+f"(c[3])
                 : "r"(a[0]), "r"(a[1]), "r"(a[2]), "r"(a[3]), "r"(b[0]), "r"(b[1]));
}

// ---------------- init ----------------
__global__ void zero_all_kernel() {
    int i = blockIdx.x * blockDim.x + threadIdx.x;
    if (i < NN) g_CNT[i] = 0;
    if (i < (NP - NN) * C1) g_EF[(size_t)NN * C1 + i] = __float2half(0.f);
}

// ---------------- combined prep ----------------
#define PX_ITEMS (NP * FI / 4)
#define PW1_ITEMS (C1 * FI)
#define PW2_ITEMS (NC * C1)

__global__ void prep_all_kernel(const float* __restrict__ x,
                                const float* __restrict__ W1,
                                const float* __restrict__ W2) {
    int i = blockIdx.x * blockDim.x + threadIdx.x;
    if (i < PX_ITEMS) {
        int row = i >> 6;
        float4 v = (row < NN) ? *(const float4*)(x + (size_t)i * 4)
                              : make_float4(0.f, 0.f, 0.f, 0.f);
        __half2 h0 = __floats2half2_rn(v.x, v.y);
        __half2 h1 = __floats2half2_rn(v.z, v.w);
        *(__half2*)&g_XF[(size_t)i * 4]     = h0;
        *(__half2*)&g_XF[(size_t)i * 4 + 2] = h1;
    } else if (i < PX_ITEMS + PW1_ITEMS) {
        int idx = i - PX_ITEMS;
        int c = idx >> 8;
        int k = idx & 255;
        g_W1F[idx] = __float2half(W1[(size_t)(c >> 6) * (FI * HD) + (size_t)k * HD + (c & 63)]);
    } else if (i < PX_ITEMS + PW1_ITEMS + PW2_ITEMS) {
        int idx = i - PX_ITEMS - PW1_ITEMS;
        int c = idx >> 9;
        int k = idx & 511;
        g_W2F[idx] = __float2half(W2[(size_t)k * NC + c]);
    }
}

// ---------------- GEMM1: 1-pass fp16 mma.sync, 2 CTA/SM, fused a1 dots ----------------
__global__ __launch_bounds__(256, 2) void gemm1_mma_kernel(const float* __restrict__ a1p) {
    __shared__ unsigned AH[2][128][12];
    __shared__ unsigned BH[2][128][12];

    const int tid  = threadIdx.x;
    const int lane = tid & 31;
    const int wid  = tid >> 5;
    const int wm   = wid >> 1;
    const int wn   = wid & 1;
    const int bm   = blockIdx.x * 128;
    const int bn   = blockIdx.y * 128;

    float acc[2][8][4];
#pragma unroll
    for (int i = 0; i < 2; i++)
#pragma unroll
        for (int j = 0; j < 8; j++)
#pragma unroll
            for (int k = 0; k < 4; k++) acc[i][j][k] = 0.f;

    const unsigned aBase = smem_u32(AH);
    const unsigned bBase = smem_u32(BH);
    const unsigned BUF = 128 * 48;     // bytes per buffer

    unsigned aadr[2];
#pragma unroll
    for (int mt = 0; mt < 2; mt++) {
        int r = wm * 32 + mt * 16 + (lane & 15);
        int cb = (lane >> 4) * 16;
        aadr[mt] = aBase + r * 48 + cb;
    }
    unsigned badr[4];
#pragma unroll
    for (int np = 0; np < 4; np++) {
        int r = wn * 64 + np * 16 + ((lane >> 4) << 3) + (lane & 7);
        int cb = ((lane >> 3) & 1) * 16;
        badr[np] = bBase + r * 48 + cb;
    }

    const int arow = tid >> 1;
    const int ach  = tid & 1;
    const unsigned short* xf = (const unsigned short*)g_XF;
    const unsigned short* wf = (const unsigned short*)g_W1F;
    size_t aIdx = (size_t)(bm + arow) * FI + ach * 8;
    size_t bIdx = (size_t)(bn + arow) * FI + ach * 8;

    // preload tile 0 into buf 0
    *(uint4*)&AH[0][arow][ach * 4] = *(const uint4*)(xf + aIdx);
    *(uint4*)&BH[0][arow][ach * 4] = *(const uint4*)(wf + bIdx);
    __syncthreads();

    for (int it = 0; it < 16; ++it) {
        const int b = it & 1;
        const unsigned boff = b * BUF;

        unsigned ah[2][4];
#pragma unroll
        for (int mt = 0; mt < 2; mt++)
            ldm4(ah[mt][0], ah[mt][1], ah[mt][2], ah[mt][3], aadr[mt] + boff);

        uint4 va, vb;
        if (it < 15) {
            const int k1 = (it + 1) * 16;
            va = *(const uint4*)(xf + aIdx + k1);
            vb = *(const uint4*)(wf + bIdx + k1);
        }

#pragma unroll
        for (int np = 0; np < 4; np++) {
            unsigned bh[4];
            ldm4(bh[0], bh[1], bh[2], bh[3], badr[np] + boff);
#pragma unroll
            for (int mt = 0; mt < 2; mt++) {
                mmaf16(acc[mt][np * 2],     ah[mt], bh);
                mmaf16(acc[mt][np * 2 + 1], ah[mt], bh + 2);
            }
        }

        if (it < 15) {
            int nb = b ^ 1;
            *(uint4*)&AH[nb][arow][ach * 4] = va;
            *(uint4*)&BH[nb][arow][ach * 4] = vb;
        }
        __syncthreads();
    }

    // write H1 fp16 (group-major: group = bn>>8)
    const int grp = bn >> 8;
    const int lbase = (bn & 255) + wn * 64 + (lane & 3) * 2;
    __half* Hgrp = g_H1 + (size_t)grp * NN * 256;
#pragma unroll
    for (int mt = 0; mt < 2; mt++) {
        int r = bm + wm * 32 + mt * 16 + (lane >> 2);
#pragma unroll
        for (int nt = 0; nt < 8; nt++) {
            if (r < NN) {
                __half2 hv = __floats2half2_rn(acc[mt][nt][0], acc[mt][nt][1]);
                *(__half2*)&Hgrp[(size_t)r * 256 + lbase + nt * 8] = hv;
            }
            if (r + 8 < NN) {
                __half2 hv = __floats2half2_rn(acc[mt][nt][2], acc[mt][nt][3]);
                *(__half2*)&Hgrp[(size_t)(r + 8) * 256 + lbase + nt * 8] = hv;
            }
        }
    }

    // fused a1 dots
    const int hh = blockIdx.y * 2 + wn;
    const float* av = a1p + hh * (2 * HD);
    const float* tv = av + HD;
    float sdot[4], tdot[4];
#pragma unroll
    for (int i = 0; i < 4; i++) { sdot[i] = 0.f; tdot[i] = 0.f; }
#pragma unroll
    for (int mt = 0; mt < 2; mt++) {
#pragma unroll
        for (int nt = 0; nt < 8; nt++) {
            int cip = nt * 8 + (lane & 3) * 2;
            float a0 = __ldg(av + cip);
            float a1e = __ldg(av + cip + 1);
            float t0 = __ldg(tv + cip);
            float t1e = __ldg(tv + cip + 1);
            sdot[mt * 2 + 0] += acc[mt][nt][0] * a0 + acc[mt][nt][1] * a1e;
            tdot[mt * 2 + 0] += acc[mt][nt][0] * t0 + acc[mt][nt][1] * t1e;
            sdot[mt * 2 + 1] += acc[mt][nt][2] * a0 + acc[mt][nt][3] * a1e;
            tdot[mt * 2 + 1] += acc[mt][nt][2] * t0 + acc[mt][nt][3] * t1e;
        }
    }
#pragma unroll
    for (int i = 0; i < 4; i++) {
        sdot[i] += __shfl_xor_sync(0xffffffffu, sdot[i], 1);
        sdot[i] += __shfl_xor_sync(0xffffffffu, sdot[i], 2);
        tdot[i] += __shfl_xor_sync(0xffffffffu, tdot[i], 1);
        tdot[i] += __shfl_xor_sync(0xffffffffu, tdot[i], 2);
    }
    if ((lane & 3) == 0) {
#pragma unroll
        for (int mt = 0; mt < 2; mt++) {
#pragma unroll
            for (int hb = 0; hb < 2; hb++) {
                int r = bm + wm * 32 + mt * 16 + (lane >> 2) + hb * 8;
                if (r < NN) {
                    g_ASRC1[r * NH + hh] = sdot[mt * 2 + hb];
                    g_ATGT1[r * NH + hh] = tdot[mt * 2 + hb];
                }
            }
        }
    }
}

// ---------------- histogram ----------------
__global__ void hist_kernel(const int* __restrict__ src) {
    int e = blockIdx.x * blockDim.x + threadIdx.x;
    if (e >= NE) return;
    atomicAdd(&g_CNT[src[e]], 1);
}

// ---------------- counting-sort scan ----------------
#define SBLK 512
#define NBLK 98

__global__ void scan_block_kernel() {
    __shared__ int sh[SBLK];
    int t = threadIdx.x;
    int i = blockIdx.x * SBLK + t;
    int v = (i < NN) ? g_CNT[i] : 0;
    sh[t] = v;
    __syncthreads();
#pragma unroll
    for (int off = 1; off < SBLK; off <<= 1) {
        int add = (t >= off) ? sh[t - off] : 0;
        __syncthreads();
        sh[t] += add;
        __syncthreads();
    }
    if (i < NN) g_OFFS[i] = sh[t] - v;
    if (t == SBLK - 1) g_AUX[blockIdx.x] = sh[SBLK - 1];
}

// scan_add with aux prefix computed per-block in smem (scan_aux folded in)
__global__ void scan_add_kernel() {
    __shared__ int sh[128];
    int t = threadIdx.x;
    if (t < 128) sh[t] = (t < NBLK) ? g_AUX[t] : 0;
    __syncthreads();
#pragma unroll
    for (int off = 1; off < 128; off <<= 1) {
        int add = (t < 128 && t >= off) ? sh[t - off] : 0;
        __syncthreads();
        if (t < 128) sh[t] += add;
        __syncthreads();
    }
    int base = (blockIdx.x > 0) ? sh[blockIdx.x - 1] : 0;   // exclusive prefix
    int i = blockIdx.x * SBLK + t;
    if (i < NN) {
        int v = g_OFFS[i] + base;
        g_OFFS[i] = v;
        g_CURSOR[i] = v;
    }
    if (i == 0) g_OFFS[NN] = NE;
}

__global__ void sort_kernel(const int* __restrict__ src, const int* __restrict__ tgt) {
    int e = blockIdx.x * blockDim.x + threadIdx.x;
    if (e >= NE) return;
    int s = src[e];
    int pos = atomicAdd(&g_CURSOR[s], 1);
    g_TSORT[pos] = tgt[e];
}

// ---------------- gather1 (per head-group pass), unroll 4 ----------------
__global__ void gather1_kernel(const float* __restrict__ b1, int gp) {
    int w = (blockIdx.x * blockDim.x + threadIdx.x) >> 5;
    int lane = threadIdx.x & 31;
    if (w >= NN) return;
    int beg = g_OFFS[w];
    int end = g_OFFS[w + 1];
    int hsel = lane >> 4;
    int hq = gp * 4 + (lane & 3);
    float asrc = g_ASRC1[w * NH + hq];
    float den[2] = {0.f, 0.f};
    float4 acc[2];
    acc[0] = make_float4(0.f, 0.f, 0.f, 0.f);
    acc[1] = make_float4(0.f, 0.f, 0.f, 0.f);
    const __half* Hbase = g_H1 + (size_t)gp * NN * 256;

    int i = beg;
    for (; i + 4 <= end; i += 4) {
        int tn[4];
        float ee[4];
#pragma unroll
        for (int j = 0; j < 4; j++) tn[j] = g_TSORT[i + j];
#pragma unroll
        for (int j = 0; j < 4; j++)
            ee[j] = expf(lrelu(asrc + g_ATGT1[tn[j] * NH + hq]));
#pragma unroll
        for (int h = 0; h < 2; h++) {
#pragma unroll
            for (int j = 0; j < 4; j++) {
                float ev = __shfl_sync(0xffffffffu, ee[j], h * 2 + hsel, 4);
                den[h] += ev;
                const __half* r = Hbase + (size_t)tn[j] * 256 + h * 128 + lane * 4;
                float2 fa = __half22float2(*(const __half2*)r);
                float2 fb = __half22float2(*(const __half2*)(r + 2));
                acc[h].x += ev * fa.x;
                acc[h].y += ev * fa.y;
                acc[h].z += ev * fb.x;
                acc[h].w += ev * fb.y;
            }
        }
    }
    for (; i < end; i++) {
        int t0 = g_TSORT[i];
        float e0 = expf(lrelu(asrc + g_ATGT1[t0 * NH + hq]));
        const __half* r0 = Hbase + (size_t)t0 * 256;
#pragma unroll
        for (int h = 0; h < 2; h++) {
            float ev0 = __shfl_sync(0xffffffffu, e0, h * 2 + hsel, 4);
            den[h] += ev0;
            float2 fa = __half22float2(*(const __half2*)(r0 + h * 128 + lane * 4));
            float2 fb = __half22float2(*(const __half2*)(r0 + h * 128 + lane * 4 + 2));
            acc[h].x += ev0 * fa.x;
            acc[h].y += ev0 * fa.y;
            acc[h].z += ev0 * fb.x;
            acc[h].w += ev0 * fb.y;
        }
    }
#pragma unroll
    for (int h = 0; h < 2; h++) {
        float r = 1.f / (den[h] + 1e-10f);
        int colg = gp * 256 + h * 128 + lane * 4;
        float4 bb = *(const float4*)&b1[colg];
        float v0 = eluf(acc[h].x * r + bb.x);
        float v1 = eluf(acc[h].y * r + bb.y);
        float v2 = eluf(acc[h].z * r + bb.z);
        float v3 = eluf(acc[h].w * r + bb.w);
        size_t base = (size_t)w * C1 + colg;
        *(__half2*)&g_EF[base]     = __floats2half2_rn(v0, v1);
        *(__half2*)&g_EF[base + 2] = __floats2half2_rn(v2, v3);
    }
}

// ---------------- GEMM2: 1-pass fp16, resident-B, double-buffered A, fused alpha2 -----
#define G2_BSTR 260                       // words per B row (1040 B)
#define G2_BWORDS (48 * G2_BSTR)
#define G2_AWORDS (2 * 128 * 12)
#define G2_SMEM_BYTES ((G2_BWORDS + G2_AWORDS) * 4)

__global__ __launch_bounds__(256) void gemm2_mma_kernel(const float* __restrict__ a2) {
    extern __shared__ unsigned g2s[];
    unsigned* sB = g2s;
    unsigned* sA = g2s + G2_BWORDS;     // [2][128][12]

    const int tid  = threadIdx.x;
    const int lane = tid & 31;
    const int wid  = tid >> 5;
    const int bm   = blockIdx.x * 128;

    for (int idx = tid; idx < 48 * 256; idx += 256) {
        int row = idx >> 8;
        int wq  = idx & 255;
        unsigned v = (row < NC) ? ((const unsigned*)g_W2F)[row * 256 + wq] : 0u;
        sB[row * G2_BSTR + wq] = v;
    }

    float acc[5][4];
#pragma unroll
    for (int j = 0; j < 5; j++)
#pragma unroll
        for (int k = 0; k < 4; k++) acc[j][k] = 0.f;

    const unsigned aBase = smem_u32(sA);
    const unsigned bBase = smem_u32(sB);
    const unsigned ABUF = 128 * 48;

    unsigned aadr;
    {
        int r = wid * 16 + (lane & 15);
        int cb = (lane >> 4) * 16;
        aadr = aBase + r * 48 + cb;
    }
    unsigned badr[3];
#pragma unroll
    for (int np = 0; np < 3; np++) {
        int r = np * 16 + ((lane >> 4) << 3) + (lane & 7);
        int cb = ((lane >> 3) & 1) * 16;
        badr[np] = bBase + r * (G2_BSTR * 4) + cb;
    }

    const int arow = tid >> 1;
    const int ach  = tid & 1;
    const unsigned short* ef = (const unsigned short*)g_EF;
    size_t aIdx = (size_t)(bm + arow) * C1 + ach * 8;

    *(uint4*)(sA + (size_t)arow * 12 + ach * 4) = *(const uint4*)(ef + aIdx);
    __syncthreads();

    for (int it = 0; it < 32; ++it) {
        const int b = it & 1;
        const unsigned aoff = b * ABUF;
        const unsigned koff = it * 32;

        unsigned ah[4];
        ldm4(ah[0], ah[1], ah[2], ah[3], aadr + aoff);

        uint4 va;
        if (it < 31) va = *(const uint4*)(ef + aIdx + (it + 1) * 16);

#pragma unroll
        for (int np = 0; np < 3; np++) {
            unsigned bh[4];
            ldm4(bh[0], bh[1], bh[2], bh[3], badr[np] + koff);
            mmaf16(acc[np * 2], ah, bh);
            if (np < 2) mmaf16(acc[np * 2 + 1], ah, bh + 2);
        }

        if (it < 31) {
            int nb = b ^ 1;
            *(uint4*)(sA + (size_t)nb * (128 * 12) + (size_t)arow * 12 + ach * 4) = va;
        }
        __syncthreads();
    }

    int r0 = bm + wid * 16 + (lane >> 2);
    int r1 = r0 + 8;
    float s0 = 0.f, s1 = 0.f, t0 = 0.f, t1 = 0.f;
#pragma unroll
    for (int nt = 0; nt < 5; nt++) {
        int c = nt * 8 + (lane & 3) * 2;
        float a0 = __ldg(a2 + c);
        float a1e = __ldg(a2 + c + 1);
        float b0 = __ldg(a2 + NC + c);
        float b1e = __ldg(a2 + NC + c + 1);
        if (r0 < NN) {
            float2 v;
            v.x = acc[nt][0];
            v.y = acc[nt][1];
            *(float2*)&g_H2[(size_t)r0 * NC + c] = v;
        }
        if (r1 < NN) {
            float2 v;
            v.x = acc[nt][2];
            v.y = acc[nt][3];
            *(float2*)&g_H2[(size_t)r1 * NC + c] = v;
        }
        s0 += acc[nt][0] * a0 + acc[nt][1] * a1e;
        t0 += acc[nt][0] * b0 + acc[nt][1] * b1e;
        s1 += acc[nt][2] * a0 + acc[nt][3] * a1e;
        t1 += acc[nt][2] * b0 + acc[nt][3] * b1e;
    }
    s0 += __shfl_xor_sync(0xffffffffu, s0, 1);
    s0 += __shfl_xor_sync(0xffffffffu, s0, 2);
    s1 += __shfl_xor_sync(0xffffffffu, s1, 1);
    s1 += __shfl_xor_sync(0xffffffffu, s1, 2);
    t0 += __shfl_xor_sync(0xffffffffu, t0, 1);
    t0 += __shfl_xor_sync(0xffffffffu, t0, 2);
    t1 += __shfl_xor_sync(0xffffffffu, t1, 1);
    t1 += __shfl_xor_sync(0xffffffffu, t1, 2);
    if ((lane & 3) == 0) {
        if (r0 < NN) {
            g_ASRC2[r0] = s0;
            g_ATGT2[r0] = t0;
        }
        if (r1 < NN) {
            g_ASRC2[r1] = s1;
            g_ATGT2[r1] = t1;
        }
    }
}

// ---------------- gather2 + log_softmax fused, unroll 2 ----------------
__global__ void gather2_logsm_kernel(const float* __restrict__ b2, float* __restrict__ out) {
    int w = (blockIdx.x * blockDim.x + threadIdx.x) >> 5;
    int lane = threadIdx.x & 31;
    if (w >= NN) return;
    int beg = g_OFFS[w];
    int end = g_OFFS[w + 1];
    float asrc = g_ASRC2[w];
    bool has2 = lane < 8;
    float acc1 = 0.f;
    float acc2 = 0.f;
    float den = 0.f;
    int i = beg;
    for (; i + 2 <= end; i += 2) {
        int t0 = g_TSORT[i];
        int t1 = g_TSORT[i + 1];
        float ev0 = expf(lrelu(asrc + g_ATGT2[t0]));
        float ev1 = expf(lrelu(asrc + g_ATGT2[t1]));
        den += ev0 + ev1;
        acc1 += ev0 * g_H2[t0 * NC + lane] + ev1 * g_H2[t1 * NC + lane];
        if (has2) acc2 += ev0 * g_H2[t0 * NC + 32 + lane] + ev1 * g_H2[t1 * NC + 32 + lane];
    }
    if (i < end) {
        int t = g_TSORT[i];
        float ev = expf(lrelu(asrc + g_ATGT2[t]));
        den += ev;
        acc1 += ev * g_H2[t * NC + lane];
        if (has2) acc2 += ev * g_H2[t * NC + 32 + lane];
    }
    float r = 1.f / (den + 1e-10f);
    float v1 = acc1 * r + b2[lane];
    float v2 = has2 ? (acc2 * r + b2[32 + lane]) : -3.0e38f;
    float m = wmax(fmaxf(v1, v2));
    float ssum = expf(v1 - m) + (has2 ? expf(v2 - m) : 0.f);
    ssum = wsum(ssum);
    float l = logf(ssum);
    out[w * NC + lane] = v1 - m - l;
    if (has2) out[w * NC + 32 + lane] = v2 - m - l;
}

// ---------------- launch ----------------
extern "C" void kernel_launch(void* const* d_in, const int* in_sizes, int n_in,
                              void* d_out, int out_size) {
    const float* x  = (const float*)d_in[0];
    const int*   el = (const int*)d_in[1];
    const float* W1 = (const float*)d_in[2];
    const float* a1 = (const float*)d_in[3];
    const float* b1 = (const float*)d_in[4];
    const float* W2 = (const float*)d_in[5];
    const float* a2 = (const float*)d_in[6];
    const float* b2 = (const float*)d_in[7];
    float* out = (float*)d_out;
    const int* src = el;
    const int* tgt = el + NE;

    cudaFuncSetAttribute(gemm2_mma_kernel,
                         cudaFuncAttributeMaxDynamicSharedMemorySize, G2_SMEM_BYTES);

    // order chosen so launch index 3 (the one ncu captures) is gemm1
    int prep_items = PX_ITEMS + PW1_ITEMS + PW2_ITEMS;
    prep_all_kernel<<<(prep_items + 255) / 256, 256>>>(x, W1, W2);       // 0
    zero_all_kernel<<<((NP - NN) * C1 + 255) / 256, 256>>>();            // 1
    hist_kernel<<<(NE + 255) / 256, 256>>>(src);                          // 2

    dim3 g1(NP / 128, C1 / 128);
    gemm1_mma_kernel<<<g1, 256>>>(a1);                                    // 3

    scan_block_kernel<<<NBLK, SBLK>>>();                                  // 4
    scan_add_kernel<<<NBLK, SBLK>>>();                                    // 5
    sort_kernel<<<(NE + 255) / 256, 256>>>(src, tgt);                     // 6

    int warp_grid = (NN * 32 + 255) / 256;
    gather1_kernel<<<warp_grid, 256>>>(b1, 0);                            // 7
    gather1_kernel<<<warp_grid, 256>>>(b1, 1);                            // 8

    gemm2_mma_kernel<<<NP / 128, 256, G2_SMEM_BYTES>>>(a2);               // 9
    gather2_logsm_kernel<<<warp_grid, 256>>>(b2, out);                    // 10
}